// round 1
// baseline (speedup 1.0000x reference)
#include <cuda_runtime.h>

// Problem constants
#define N_IMG 4
#define C_IN  256
#define C_MID 64
#define H     64
#define W     64
#define HW    4096
#define E_OUT 100
#define KK    25
#define MASK_STRIDE 116   // 4*28 padded to kill bank conflicts (116 mod 32 = 20)

// Scratch (device globals; no allocation allowed)
__device__ float g_comp[N_IMG * C_MID * HW];            // [n][oc][h*64+w]   4 MB
__device__ float g_mask[N_IMG * HW * MASK_STRIDE];      // [n][p][ij*28+k]   7.6 MB

// ---------------------------------------------------------------------------
// Kernel 1: 1x1 conv, 256 -> 64 channels.
// One thread per pixel, 64 accumulators, weights transposed in smem to
// [c][oc] so inner loop is LDS.128 (4 oc per load) -> LDS:FMA = 1:4.
// ---------------------------------------------------------------------------
__global__ void __launch_bounds__(128) conv1x1_kernel(
    const float* __restrict__ x,
    const float* __restrict__ w_comp,
    const float* __restrict__ b_comp) {
  extern __shared__ float wt[];  // [256][64] = 64 KB
  int tid = threadIdx.x;
  for (int i = tid; i < C_IN * C_MID; i += 128) {
    int oc = i >> 8;       // w_comp layout [oc][c]
    int c  = i & 255;
    wt[c * 64 + oc] = w_comp[i];
  }
  __syncthreads();

  int gp = blockIdx.x * 128 + tid;        // 0..16383
  int n = gp >> 12, p = gp & 4095;
  const float* xb = x + ((size_t)n * C_IN) * HW + p;

  float acc[64];
  #pragma unroll
  for (int oc = 0; oc < 64; oc++) acc[oc] = __ldg(b_comp + oc);

  #pragma unroll 2
  for (int c = 0; c < C_IN; c++) {
    float xv = __ldg(xb + c * HW);
    const float4* wr = (const float4*)(wt + c * 64);
    #pragma unroll
    for (int q = 0; q < 16; q++) {
      float4 w4 = wr[q];
      acc[q*4+0] += w4.x * xv;
      acc[q*4+1] += w4.y * xv;
      acc[q*4+2] += w4.z * xv;
      acc[q*4+3] += w4.w * xv;
    }
  }
  float* ob = g_comp + ((size_t)n * C_MID) * HW + p;
  #pragma unroll
  for (int oc = 0; oc < 64; oc++) ob[oc * HW] = acc[oc];
}

// ---------------------------------------------------------------------------
// Kernel 2: 3x3 conv (64 -> 100) fused with pixel-shuffle softmax.
// Block: 8x16 spatial tile of one image. Thread = (pixel-pair, ij).
// Each thread accumulates all 25 taps for its subpixel -> softmax in regs.
// Weights staged in smem k-contiguous so LDS.128 feeds 4 FMAs; two pixels
// per thread amortize weight loads -> LDS:FMA ~ 1:5.
// ---------------------------------------------------------------------------
#define K2_TH 8
#define K2_TW 16
#define K2_ICC 16
#define CT_ROW 18
#define WS_FLOATS (K2_ICC * 9 * 4 * 28)      // 16128
#define CT_FLOATS (K2_ICC * 10 * CT_ROW)     // 2880

__global__ void __launch_bounds__(256) conv3x3_softmax_kernel(
    const float* __restrict__ w_enc,
    const float* __restrict__ b_enc) {
  extern __shared__ float sm[];
  float* ws = sm;               // [icl][tap][ij][28]
  float* ct = sm + WS_FLOATS;   // [icl][yy(10)][xx(18)]

  int tid = threadIdx.x;
  int ij  = tid & 3;
  int tp  = tid >> 2;           // 0..63 pixel-pair index
  int r   = tp >> 3;            // row in tile 0..7
  int c0  = (tp & 7) * 2;       // col in tile (pair base) 0,2,..,14

  int b  = blockIdx.x;
  int n  = b >> 5;
  int t  = b & 31;
  int h0 = (t >> 2) * K2_TH;
  int w0 = (t & 3) * K2_TW;

  float acc0[25], acc1[25];
  #pragma unroll
  for (int k = 0; k < 25; k++) { acc0[k] = 0.f; acc1[k] = 0.f; }

  for (int icc = 0; icc < C_MID / K2_ICC; icc++) {
    int ic0 = icc * K2_ICC;
    // stage weights: ws[((icl*9+tap)*4+ij)*28 + k] = w_enc[e=k*4+ij][ic][tap]
    for (int i = tid; i < K2_ICC * 9 * 4 * 25; i += 256) {
      int k   = i % 25;
      int j2  = (i / 25) & 3;
      int tap = (i / 100) % 9;
      int icl = i / 900;
      int e = k * 4 + j2;
      ws[((icl * 9 + tap) * 4 + j2) * 28 + k] =
          __ldg(w_enc + (e * C_MID + ic0 + icl) * 9 + tap);
    }
    // stage comp tile with 1-px halo, zero padded
    for (int i = tid; i < CT_FLOATS; i += 256) {
      int xx  = i % CT_ROW;
      int yy  = (i / CT_ROW) % 10;
      int icl = i / (10 * CT_ROW);
      int gh = h0 - 1 + yy, gw = w0 - 1 + xx;
      float v = 0.f;
      if (gh >= 0 && gh < H && gw >= 0 && gw < W)
        v = g_comp[((size_t)(n * C_MID + ic0 + icl) << 12) + gh * W + gw];
      ct[(icl * 10 + yy) * CT_ROW + xx] = v;
    }
    __syncthreads();

    for (int icl = 0; icl < K2_ICC; icl++) {
      #pragma unroll
      for (int ty = 0; ty < 3; ty++) {
        #pragma unroll
        for (int tx = 0; tx < 3; tx++) {
          float cv0 = ct[(icl * 10 + r + ty) * CT_ROW + c0 + tx];
          float cv1 = ct[(icl * 10 + r + ty) * CT_ROW + c0 + 1 + tx];
          const float* wb = ws + ((icl * 9 + ty * 3 + tx) * 4 + ij) * 28;
          const float4* wb4 = (const float4*)wb;
          #pragma unroll
          for (int q = 0; q < 6; q++) {
            float4 w4 = wb4[q];
            acc0[q*4+0] += w4.x * cv0;  acc1[q*4+0] += w4.x * cv1;
            acc0[q*4+1] += w4.y * cv0;  acc1[q*4+1] += w4.y * cv1;
            acc0[q*4+2] += w4.z * cv0;  acc1[q*4+2] += w4.z * cv1;
            acc0[q*4+3] += w4.w * cv0;  acc1[q*4+3] += w4.w * cv1;
          }
          float wl = wb[24];
          acc0[24] += wl * cv0;  acc1[24] += wl * cv1;
        }
      }
    }
    __syncthreads();
  }

  // bias
  #pragma unroll
  for (int k = 0; k < 25; k++) {
    float bb = __ldg(b_enc + k * 4 + ij);
    acc0[k] += bb; acc1[k] += bb;
  }

  // softmax over the 25 taps (in registers), then store
  float m0 = acc0[0], m1 = acc1[0];
  #pragma unroll
  for (int k = 1; k < 25; k++) { m0 = fmaxf(m0, acc0[k]); m1 = fmaxf(m1, acc1[k]); }
  float s0 = 0.f, s1 = 0.f;
  #pragma unroll
  for (int k = 0; k < 25; k++) {
    acc0[k] = __expf(acc0[k] - m0); s0 += acc0[k];
    acc1[k] = __expf(acc1[k] - m1); s1 += acc1[k];
  }
  float inv0 = 1.0f / s0, inv1 = 1.0f / s1;

  int p0 = (h0 + r) * W + w0 + c0;
  float* mp0 = g_mask + (size_t)(n * HW + p0) * MASK_STRIDE + ij * 28;
  float* mp1 = mp0 + MASK_STRIDE;
  #pragma unroll
  for (int k = 0; k < 25; k++) {
    mp0[k] = acc0[k] * inv0;
    mp1[k] = acc1[k] * inv1;
  }
}

// ---------------------------------------------------------------------------
// Kernel 3: CARAFE reassembly.
// out[n,c,2h+i,2w+j] = sum_k x_pad[n,c,h+dy,w+dx] * mask[n,k,i,j,h,w]
// Key reuse: the 25-value x window is identical for all 4 subpixels -> load
// once to registers, do 100 FMAs. Block = 8x8 low-res tile; thread=(pix,cgrp).
// ---------------------------------------------------------------------------
#define XS_STRIDE 148   // channel stride: 148 mod 32 = 20 -> 4 channels on distinct banks

__global__ void __launch_bounds__(256) reassemble_kernel(
    const float* __restrict__ x,
    float* __restrict__ out) {
  __shared__ float ms[64 * MASK_STRIDE];  // 29 KB mask tile
  __shared__ float xs[8 * XS_STRIDE];     // x chunk: 8 channels x 12x12 halo

  int tid = threadIdx.x;
  int cg  = tid & 3;
  int pix = tid >> 2;          // 0..63
  int r = pix >> 3, cl = pix & 7;

  int b  = blockIdx.x;
  int n  = b >> 6;
  int t  = b & 63;
  int h0 = (t >> 3) * 8, w0 = (t & 7) * 8;

  // stage mask tile once
  for (int i = tid; i < 64 * MASK_STRIDE; i += 256) {
    int pp  = i / MASK_STRIDE;
    int off = i - pp * MASK_STRIDE;
    int p = (h0 + (pp >> 3)) * W + w0 + (pp & 7);
    ms[i] = g_mask[(size_t)(n * HW + p) * MASK_STRIDE + off];
  }

  for (int cc = 0; cc < C_IN / 8; cc++) {
    __syncthreads();
    // stage 8-channel x chunk with 2-px halo (zero padded)
    for (int i = tid; i < 8 * 144; i += 256) {
      int ch  = i / 144;
      int rem = i - ch * 144;
      int yy = rem / 12, xx = rem - yy * 12;
      int gh = h0 - 2 + yy, gw = w0 - 2 + xx;
      float v = 0.f;
      if (gh >= 0 && gh < H && gw >= 0 && gw < W)
        v = __ldg(x + ((size_t)(n * C_IN + cc * 8 + ch) << 12) + gh * W + gw);
      xs[ch * XS_STRIDE + rem] = v;
    }
    __syncthreads();

    #pragma unroll
    for (int s = 0; s < 2; s++) {
      int ch = cg * 2 + s;
      float xw[25];
      #pragma unroll
      for (int dy = 0; dy < 5; dy++)
        #pragma unroll
        for (int dx = 0; dx < 5; dx++)
          xw[dy * 5 + dx] = xs[ch * XS_STRIDE + (r + dy) * 12 + cl + dx];

      float res[4];
      #pragma unroll
      for (int ij2 = 0; ij2 < 4; ij2++) {
        const float* mb = ms + pix * MASK_STRIDE + ij2 * 28;
        const float4* mb4 = (const float4*)mb;
        float a = 0.f;
        #pragma unroll
        for (int q = 0; q < 6; q++) {
          float4 m4 = mb4[q];
          a += m4.x * xw[q*4+0] + m4.y * xw[q*4+1]
             + m4.z * xw[q*4+2] + m4.w * xw[q*4+3];
        }
        a += mb[24] * xw[24];
        res[ij2] = a;
      }

      int c_glob = cc * 8 + ch;
      float* ob = out + ((size_t)(n * C_IN + c_glob) * 128 + 2 * (h0 + r)) * 128
                      + 2 * (w0 + cl);
      ((float2*)ob)[0]         = make_float2(res[0], res[1]);   // i=0, j=0,1
      ((float2*)(ob + 128))[0] = make_float2(res[2], res[3]);   // i=1, j=0,1
    }
  }
}

// ---------------------------------------------------------------------------
extern "C" void kernel_launch(void* const* d_in, const int* in_sizes, int n_in,
                              void* d_out, int out_size) {
  const float* x      = (const float*)d_in[0];
  const float* w_comp = (const float*)d_in[1];
  const float* b_comp = (const float*)d_in[2];
  const float* w_enc  = (const float*)d_in[3];
  const float* b_enc  = (const float*)d_in[4];
  float* out = (float*)d_out;

  cudaFuncSetAttribute(conv1x1_kernel,
                       cudaFuncAttributeMaxDynamicSharedMemorySize, 65536);
  cudaFuncSetAttribute(conv3x3_softmax_kernel,
                       cudaFuncAttributeMaxDynamicSharedMemorySize,
                       (WS_FLOATS + CT_FLOATS) * 4);

  conv1x1_kernel<<<128, 128, 65536>>>(x, w_comp, b_comp);
  conv3x3_softmax_kernel<<<128, 256, (WS_FLOATS + CT_FLOATS) * 4>>>(w_enc, b_enc);
  reassemble_kernel<<<256, 256>>>(x, out);
}